// round 1
// baseline (speedup 1.0000x reference)
#include <cuda_runtime.h>
#include <math.h>

// Problem shape (fixed by the dataset): N=16, T=256, U=128, V=256, blank = V-1.
#define N_  16
#define T_  256
#define U_  128
#define V_  256
#define DD  (T_ + U_ - 1)   // 383 anti-diagonals
#define DD_PAD 384

#define NEGF (-1e30f)

// Scratch (allocation-free rule: __device__ globals).
// Anti-diagonal-major layout: [n][t+u][u]  -> wavefront reads are coalesced.
__device__ float g_blank[N_ * DD_PAD * U_];   // blank lp at (n,t,u), stored at [n][t+u][u]
__device__ float g_emit [N_ * DD_PAD * U_];   // emit  lp at (n,t,u), u < U-1, stored at [n][t+u][u]
__device__ float g_cost [N_];

// ---------------------------------------------------------------------------
// Kernel 1: gather blank + emit from the (N,T,U,V) log_probs tensor into the
// diagonal-major scratch. One thread per (n,t,u) cell; 2 scattered loads each.
// ---------------------------------------------------------------------------
__global__ void __launch_bounds__(256) gather_kernel(const float* __restrict__ lp,
                                                     const int*   __restrict__ labels)
{
    int idx = blockIdx.x * blockDim.x + threadIdx.x;   // idx = (n*T + t)*U + u
    if (idx >= N_ * T_ * U_) return;
    int u = idx & (U_ - 1);
    int t = (idx >> 7) & (T_ - 1);
    int n = idx >> 15;

    const float* row = lp + (size_t)idx * V_;
    int d = t + u;
    size_t dst = ((size_t)n * DD_PAD + d) * U_ + u;

    g_blank[dst] = row[V_ - 1];
    if (u < U_ - 1) {
        int lbl = labels[n * (U_ - 1) + u];
        g_emit[dst] = row[lbl];
    }
}

// ---------------------------------------------------------------------------
// Kernel 2: wavefront DP. One block per example, one thread per u column.
// alpha(t,u) lives in a register; left neighbor via shfl_up; warp boundary via
// double-buffered shared slots => a single __syncthreads per diagonal.
// Global rows for the next diagonal are prefetched (software pipeline).
// ---------------------------------------------------------------------------
__device__ __forceinline__ float lse2(float a, float b) {
    float m = fmaxf(a, b);
    return m + log1pf(__expf(fminf(a, b) - m));
}

__global__ void __launch_bounds__(U_) dp_kernel(const int* __restrict__ lengths,
                                                const int* __restrict__ label_lengths)
{
    const int n    = blockIdx.x;
    const int u    = threadIdx.x;
    const int lane = u & 31;
    const int warp = u >> 5;

    __shared__ float bnd[2][4];   // [parity][warp] lane-31 boundary values
    if (u < 8) ((float*)bnd)[u] = NEGF;

    const int t_idx    = lengths[n] - 1;
    const int u_idx    = label_lengths[n];
    const int target_d = t_idx + u_idx;

    const float* __restrict__ bl = g_blank + (size_t)n * DD_PAD * U_;
    const float* __restrict__ em = g_emit  + (size_t)n * DD_PAD * U_;

    float a_self = NEGF;     // alpha value for column u on the last diagonal that touched it
    float saved  = 0.0f;

    // Prefetch row 0 (consumed at d=1; row index used at diag d is d-1).
    float blank_nxt = bl[u];
    float emit_nxt  = (u > 0) ? em[u - 1] : NEGF;

    __syncthreads();   // bnd init visible

    for (int d = 0; d < DD; ++d) {
        float blank_cur = blank_nxt;
        float emit_cur  = emit_nxt;
        // Prefetch row d (consumed at diag d+1). d <= DD-1 = 382 < DD_PAD rows: always valid.
        blank_nxt = bl[d * U_ + u];
        emit_nxt  = (u > 0) ? em[d * U_ + (u - 1)] : NEGF;

        // Left neighbor's alpha as of diagonal d-1.
        float left = __shfl_up_sync(0xffffffffu, a_self, 1);
        if (lane == 0)
            left = (warp > 0) ? bnd[(d + 1) & 1][warp - 1] : NEGF;

        int t = d - u;
        if (t >= 0 && t < T_) {            // cell (t,u) lies on diagonal d
            if (t == 0) {
                a_self = (u == 0) ? 0.0f : (left + emit_cur);          // alpha(0,u)
            } else if (u == 0) {
                a_self = a_self + blank_cur;                            // alpha(t,0)
            } else {
                a_self = lse2(a_self + blank_cur, left + emit_cur);     // interior
            }
            if (d == target_d && u == u_idx) saved = a_self;
        }

        if (lane == 31) bnd[d & 1][warp] = a_self;
        __syncthreads();
    }

    if (u == u_idx) {
        float blank_final = bl[target_d * U_ + u_idx];   // blank lp at (t_idx, u_idx)
        g_cost[n] = -(saved + blank_final);
    }
}

// ---------------------------------------------------------------------------
// Kernel 3: deterministic serial mean of the 16 per-example costs.
// ---------------------------------------------------------------------------
__global__ void finalize_kernel(float* __restrict__ out)
{
    float s = 0.0f;
    #pragma unroll
    for (int i = 0; i < N_; ++i) s += g_cost[i];
    out[0] = s * (1.0f / N_);
}

// ---------------------------------------------------------------------------
extern "C" void kernel_launch(void* const* d_in, const int* in_sizes, int n_in,
                              void* d_out, int out_size)
{
    const float* log_probs     = (const float*)d_in[0];
    const int*   labels        = (const int*)  d_in[1];
    const int*   lengths       = (const int*)  d_in[2];
    const int*   label_lengths = (const int*)  d_in[3];
    float*       out           = (float*)d_out;

    const int total  = N_ * T_ * U_;
    const int tpb    = 256;
    gather_kernel  <<<(total + tpb - 1) / tpb, tpb>>>(log_probs, labels);
    dp_kernel      <<<N_, U_>>>(lengths, label_lengths);
    finalize_kernel<<<1, 1>>>(out);
}

// round 2
// speedup vs baseline: 1.5424x; 1.5424x over previous
#include <cuda_runtime.h>
#include <math.h>

// Problem shape (fixed by the dataset): N=16, T=256, U=128, V=256, blank = V-1.
#define N_  16
#define T_  256
#define U_  128
#define V_  256
#define DD  (T_ + U_ - 1)   // 383 anti-diagonals
#define DD_PAD 384

#define NEGF (-1e30f)

// Scratch (allocation-free rule: __device__ globals, zero-initialized).
// SHIFTED diagonal-major layout so that diagonal d consumes exactly row d:
//   blank(n,t,u) stored at [n][t+u+1][u]
//   emit (n,t,u) stored at [n][t+u+1][u+1]
// Unwritten slots stay 0.0f; by construction they are only ever combined with
// NEG-valued alphas, so they never affect valid cells.
__device__ float4 g_blank4[N_ * DD_PAD * (U_ / 4)];
__device__ float4 g_emit4 [N_ * DD_PAD * (U_ / 4)];
__device__ float  g_cost  [N_];

// ---------------------------------------------------------------------------
// Kernel 1: gather blank + emit into shifted diagonal-major scratch.
// ---------------------------------------------------------------------------
__global__ void __launch_bounds__(256) gather_kernel(const float* __restrict__ lp,
                                                     const int*   __restrict__ labels)
{
    int idx = blockIdx.x * blockDim.x + threadIdx.x;   // idx = (n*T + t)*U + u
    if (idx >= N_ * T_ * U_) return;
    int u = idx & (U_ - 1);
    int t = (idx >> 7) & (T_ - 1);
    int n = idx >> 15;

    const float* row = lp + (size_t)idx * V_;
    int r = t + u + 1;                                  // shifted row

    float* bl = (float*)g_blank4;
    float* em = (float*)g_emit4;

    bl[((size_t)n * DD_PAD + r) * U_ + u] = row[V_ - 1];
    if (u < U_ - 1) {
        int lbl = __ldg(&labels[n * (U_ - 1) + u]);
        em[((size_t)n * DD_PAD + r) * U_ + (u + 1)] = row[lbl];
    }
}

// ---------------------------------------------------------------------------
// Kernel 2: wavefront DP. ONE WARP per example, 4 u-columns per thread.
// No barriers, no shared memory: left neighbor via a single shfl per diagonal.
// Operand rows prefetched 4 diagonals ahead through a rolling float4 buffer.
// ---------------------------------------------------------------------------
__device__ __forceinline__ float lse2(float a, float b) {
    float mx = fmaxf(a, b);
    float mn = fminf(a, b);
    return mx + __logf(1.0f + __expf(mn - mx));
}

__global__ void __launch_bounds__(32) dp_kernel(const int* __restrict__ lengths,
                                                const int* __restrict__ label_lengths)
{
    const int n  = blockIdx.x;
    const int tx = threadIdx.x;          // owns u = 4*tx .. 4*tx+3

    const float4* __restrict__ bl4 = g_blank4 + (size_t)n * DD_PAD * (U_ / 4);
    const float4* __restrict__ em4 = g_emit4  + (size_t)n * DD_PAD * (U_ / 4);

    const int t_idx  = lengths[n] - 1;
    const int u_idx  = label_lengths[n];
    const int target = t_idx + u_idx;

    // alpha registers for the 4 owned columns; NEG everywhere, seed (0,0)=0.
    float a0 = (tx == 0) ? 0.0f : NEGF;
    float a1 = NEGF, a2 = NEGF, a3 = NEGF;

    // Prefetch rows 1..4 (row d is consumed at diagonal d).
    float4 qb[4], qe[4];
#pragma unroll
    for (int k = 0; k < 4; ++k) {
        qb[k] = bl4[(size_t)(k + 1) * (U_ / 4) + tx];
        qe[k] = em4[(size_t)(k + 1) * (U_ / 4) + tx];
    }

    float saved = 0.0f;
    const bool cap = (tx == (u_idx >> 2));
    const int  ci  = u_idx & 3;

#pragma unroll 4
    for (int dd = 0; dd < DD - 1; ++dd) {      // diagonal d = dd+1
        const int d = dd + 1;
        const int s = dd & 3;
        const float4 b = qb[s];
        const float4 e = qe[s];
        // Prefetch row d+4 into the slot just freed (clamped into padding).
        int rpf = dd + 5; if (rpf > DD_PAD - 1) rpf = DD_PAD - 1;
        qb[s] = bl4[(size_t)rpf * (U_ / 4) + tx];
        qe[s] = em4[(size_t)rpf * (U_ / 4) + tx];

        // Left neighbor's alpha (column 4*tx - 1) from the previous diagonal.
        float la = __shfl_up_sync(0xffffffffu, a3, 1);
        float l0 = (tx == 0) ? NEGF : la;

        float n0 = lse2(a0 + b.x, l0 + e.x);
        float n1 = lse2(a1 + b.y, a0 + e.y);
        float n2 = lse2(a2 + b.z, a1 + e.z);
        float n3 = lse2(a3 + b.w, a2 + e.w);
        a0 = n0; a1 = n1; a2 = n2; a3 = n3;

        if (d == target && cap)
            saved = (ci == 0) ? n0 : (ci == 1) ? n1 : (ci == 2) ? n2 : n3;
    }

    if (cap) {
        const float* blf = (const float*)bl4;
        float bfin = blf[(size_t)(target + 1) * U_ + u_idx];  // blank(t_idx,u_idx)
        g_cost[n] = -(saved + bfin);
    }
}

// ---------------------------------------------------------------------------
// Kernel 3: deterministic serial mean of the 16 per-example costs.
// ---------------------------------------------------------------------------
__global__ void finalize_kernel(float* __restrict__ out)
{
    float s = 0.0f;
#pragma unroll
    for (int i = 0; i < N_; ++i) s += g_cost[i];
    out[0] = s * (1.0f / N_);
}

// ---------------------------------------------------------------------------
extern "C" void kernel_launch(void* const* d_in, const int* in_sizes, int n_in,
                              void* d_out, int out_size)
{
    const float* log_probs     = (const float*)d_in[0];
    const int*   labels        = (const int*)  d_in[1];
    const int*   lengths       = (const int*)  d_in[2];
    const int*   label_lengths = (const int*)  d_in[3];
    float*       out           = (float*)d_out;

    const int total = N_ * T_ * U_;
    gather_kernel  <<<(total + 255) / 256, 256>>>(log_probs, labels);
    dp_kernel      <<<N_, 32>>>(lengths, label_lengths);
    finalize_kernel<<<1, 1>>>(out);
}

// round 3
// speedup vs baseline: 1.7219x; 1.1164x over previous
#include <cuda_runtime.h>
#include <math.h>

// Problem shape (fixed by the dataset): N=16, T=256, U=128, V=256, blank = V-1.
#define N_  16
#define T_  256
#define U_  128
#define V_  256
#define DD  (T_ + U_ - 1)   // 383 anti-diagonals (d = 0 .. 382)
#define DD_PAD 392          // padded rows: prefetch may touch row 384

#define NEGF (-1e30f)

// Scratch (allocation-free rule: __device__ globals, zero-initialized).
// SHIFTED diagonal-major layout so that diagonal d consumes exactly row d:
//   blank(n,t,u) stored at [n][t+u+1][u]
//   emit (n,t,u) stored at [n][t+u+1][u+1]
// Unwritten slots stay 0.0f; they are only ever combined with NEG-valued
// alphas, so they never affect valid cells.
__device__ float4 g_blank4[N_ * DD_PAD * (U_ / 4)];
__device__ float4 g_emit4 [N_ * DD_PAD * (U_ / 4)];
__device__ float  g_cost  [N_];

// ---------------------------------------------------------------------------
// Kernel 1: gather blank + emit into shifted diagonal-major scratch.
// ---------------------------------------------------------------------------
__global__ void __launch_bounds__(256) gather_kernel(const float* __restrict__ lp,
                                                     const int*   __restrict__ labels)
{
    int idx = blockIdx.x * blockDim.x + threadIdx.x;   // idx = (n*T + t)*U + u
    if (idx >= N_ * T_ * U_) return;
    int u = idx & (U_ - 1);
    int t = (idx >> 7) & (T_ - 1);
    int n = idx >> 15;

    const float* row = lp + (size_t)idx * V_;
    int r = t + u + 1;                                  // shifted row

    float* bl = (float*)g_blank4;
    float* em = (float*)g_emit4;

    bl[((size_t)n * DD_PAD + r) * U_ + u] = __ldg(&row[V_ - 1]);
    if (u < U_ - 1) {
        int lbl = __ldg(&labels[n * (U_ - 1) + u]);
        em[((size_t)n * DD_PAD + r) * U_ + (u + 1)] = __ldg(&row[lbl]);
    }
}

// ---------------------------------------------------------------------------
// Kernel 2: wavefront DP. ONE WARP per example, 4 u-columns per thread.
// Manual 4x unroll with NAMED prefetch registers (no arrays -> no local mem).
// ---------------------------------------------------------------------------
__device__ __forceinline__ float lse2(float a, float b) {
    float mx = fmaxf(a, b);
    float mn = fminf(a, b);
    // mx + ln2 * log2(1 + exp2((mn-mx)*log2e))
    return mx + 0.6931471805599453f *
                __log2f(1.0f + exp2f((mn - mx) * 1.4426950408889634f));
}

// One diagonal step: consumes (b,e), updates a0..a3, captures target.
#define DP_STEP(b, e, dcur)                                                   \
    {                                                                         \
        float la = __shfl_up_sync(0xffffffffu, a3, 1);                        \
        float l0 = (tx == 0) ? NEGF : la;                                     \
        float n0 = lse2(a0 + (b).x, l0 + (e).x);                              \
        float n1 = lse2(a1 + (b).y, a0 + (e).y);                              \
        float n2 = lse2(a2 + (b).z, a1 + (e).z);                              \
        float n3 = lse2(a3 + (b).w, a2 + (e).w);                              \
        a0 = n0; a1 = n1; a2 = n2; a3 = n3;                                   \
        if ((dcur) == target && cap)                                          \
            saved = (ci == 0) ? n0 : (ci == 1) ? n1 : (ci == 2) ? n2 : n3;    \
    }

__global__ void __launch_bounds__(32) dp_kernel(const int* __restrict__ lengths,
                                                const int* __restrict__ label_lengths)
{
    const int n  = blockIdx.x;
    const int tx = threadIdx.x;          // owns u = 4*tx .. 4*tx+3

    const float4* __restrict__ bl4 = g_blank4 + (size_t)n * DD_PAD * (U_ / 4);
    const float4* __restrict__ em4 = g_emit4  + (size_t)n * DD_PAD * (U_ / 4);

    const int t_idx  = lengths[n] - 1;
    const int u_idx  = label_lengths[n];
    const int target = t_idx + u_idx;

    // alpha registers for the 4 owned columns; NEG everywhere, seed (0,0)=0.
    float a0 = (tx == 0) ? 0.0f : NEGF;
    float a1 = NEGF, a2 = NEGF, a3 = NEGF;

    float saved = 0.0f;
    const bool cap = (tx == (u_idx >> 2));
    const int  ci  = u_idx & 3;

    // Named prefetch slots holding rows 1..4 (row d is consumed at diagonal d).
    float4 qb0 = bl4[(size_t)1 * (U_ / 4) + tx], qe0 = em4[(size_t)1 * (U_ / 4) + tx];
    float4 qb1 = bl4[(size_t)2 * (U_ / 4) + tx], qe1 = em4[(size_t)2 * (U_ / 4) + tx];
    float4 qb2 = bl4[(size_t)3 * (U_ / 4) + tx], qe2 = em4[(size_t)3 * (U_ / 4) + tx];
    float4 qb3 = bl4[(size_t)4 * (U_ / 4) + tx], qe3 = em4[(size_t)4 * (U_ / 4) + tx];

    // Diagonals d = 1 .. 380 in groups of 4 (95 groups).
    for (int g = 0; g < 95; ++g) {
        const int d0 = 4 * g + 1;
        float4 b, e;

        b = qb0; e = qe0;
        qb0 = bl4[(size_t)(d0 + 4) * (U_ / 4) + tx];
        qe0 = em4[(size_t)(d0 + 4) * (U_ / 4) + tx];
        DP_STEP(b, e, d0);

        b = qb1; e = qe1;
        qb1 = bl4[(size_t)(d0 + 5) * (U_ / 4) + tx];
        qe1 = em4[(size_t)(d0 + 5) * (U_ / 4) + tx];
        DP_STEP(b, e, d0 + 1);

        b = qb2; e = qe2;
        qb2 = bl4[(size_t)(d0 + 6) * (U_ / 4) + tx];
        qe2 = em4[(size_t)(d0 + 6) * (U_ / 4) + tx];
        DP_STEP(b, e, d0 + 2);

        b = qb3; e = qe3;
        qb3 = bl4[(size_t)(d0 + 7) * (U_ / 4) + tx];
        qe3 = em4[(size_t)(d0 + 7) * (U_ / 4) + tx];
        DP_STEP(b, e, d0 + 3);
    }

    // Remainder diagonals d = 381, 382 (slots 0,1 hold rows 381,382).
    DP_STEP(qb0, qe0, 381);
    DP_STEP(qb1, qe1, 382);

    if (cap) {
        const float* blf = (const float*)g_blank4 + (size_t)n * DD_PAD * U_;
        float bfin = blf[(size_t)(target + 1) * U_ + u_idx];  // blank(t_idx,u_idx)
        g_cost[n] = -(saved + bfin);
    }
}

// ---------------------------------------------------------------------------
// Kernel 3: deterministic serial mean of the 16 per-example costs.
// ---------------------------------------------------------------------------
__global__ void finalize_kernel(float* __restrict__ out)
{
    float s = 0.0f;
#pragma unroll
    for (int i = 0; i < N_; ++i) s += g_cost[i];
    out[0] = s * (1.0f / N_);
}

// ---------------------------------------------------------------------------
extern "C" void kernel_launch(void* const* d_in, const int* in_sizes, int n_in,
                              void* d_out, int out_size)
{
    const float* log_probs     = (const float*)d_in[0];
    const int*   labels        = (const int*)  d_in[1];
    const int*   lengths       = (const int*)  d_in[2];
    const int*   label_lengths = (const int*)  d_in[3];
    float*       out           = (float*)d_out;

    const int total = N_ * T_ * U_;
    gather_kernel  <<<(total + 255) / 256, 256>>>(log_probs, labels);
    dp_kernel      <<<N_, 32>>>(lengths, label_lengths);
    finalize_kernel<<<1, 1>>>(out);
}

// round 5
// speedup vs baseline: 2.3009x; 1.3363x over previous
#include <cuda_runtime.h>
#include <math.h>

// Problem shape (fixed by the dataset): N=16, T=256, U=128, V=256, blank = V-1.
#define N_  16
#define T_  256
#define U_  128
#define V_  256
#define DD  (T_ + U_ - 1)   // 383 anti-diagonals (d = 0 .. 382)
#define DD_PAD 392          // padded rows (prefetch may touch row 384)

#define NEGF (-1e30f)

// Scratch (allocation-free rule: __device__ globals, zero-initialized).
// SHIFTED diagonal-major layout so diagonal d consumes exactly row d:
//   blank(n,t,u) stored at [n][t+u+1][u]
//   emit (n,t,u) stored at [n][t+u+1][u+1]
// Unwritten slots stay 0.0f; they only combine with NEG alphas -> harmless.
__device__ float4 g_blank4[N_ * DD_PAD * (U_ / 4)];
__device__ float4 g_emit4 [N_ * DD_PAD * (U_ / 4)];
__device__ float  g_cost  [N_];

// ---------------------------------------------------------------------------
// Kernel 1: gather. One block per (n, diagonal row r); lane c handles col c.
// Writes are fully coalesced; reads are inherently scattered (1 sector/cell).
// log_probs is read with streaming hint (__ldcs) so the 512MB stream evicts
// itself from L2 first, keeping the 6.4MB scratch resident for dp_kernel.
// ---------------------------------------------------------------------------
__global__ void __launch_bounds__(U_) gather_kernel(const float* __restrict__ lp,
                                                    const int*   __restrict__ labels)
{
    const int r = (blockIdx.x % DD) + 1;     // shifted row 1..383
    const int n = blockIdx.x / DD;
    const int c = threadIdx.x;               // column 0..127

    float* bl = (float*)g_blank4;
    float* em = (float*)g_emit4;
    const size_t rowbase = ((size_t)n * DD_PAD + r) * U_;

    // blank(t, u=c) at row r  ->  t = r-1-c
    int tb = r - 1 - c;
    if (tb >= 0 && tb < T_) {
        float v = __ldcs(lp + ((((size_t)n * T_ + tb) * U_ + c) * V_) + (V_ - 1));
        bl[rowbase + c] = v;
    }
    // emit(t, u=c-1) at row r, col c  ->  t = r-c
    int te = r - c;
    if (c >= 1 && te >= 0 && te < T_) {
        int lbl = __ldg(&labels[n * (U_ - 1) + (c - 1)]);
        float v = __ldcs(lp + ((((size_t)n * T_ + te) * U_ + (c - 1)) * V_) + lbl);
        em[rowbase + c] = v;
    }
}

// ---------------------------------------------------------------------------
// Kernel 2: wavefront DP. ONE WARP per example, 4 u-columns per thread.
// 8-row-deep software pipeline in named registers (no arrays), single shfl
// per diagonal, no barriers, no shared memory.
// ---------------------------------------------------------------------------
__device__ __forceinline__ float lse2(float a, float b) {
    float mx = fmaxf(a, b);
    float mn = fminf(a, b);
    return mx + 0.6931471805599453f *
                __log2f(1.0f + exp2f((mn - mx) * 1.4426950408889634f));
}

#define DP_STEP(b, e, dcur)                                                   \
    {                                                                         \
        float la = __shfl_up_sync(0xffffffffu, a3, 1);                        \
        float l0 = (tx == 0) ? NEGF : la;                                     \
        float n0 = lse2(a0 + (b).x, l0 + (e).x);                              \
        float n1 = lse2(a1 + (b).y, a0 + (e).y);                              \
        float n2 = lse2(a2 + (b).z, a1 + (e).z);                              \
        float n3 = lse2(a3 + (b).w, a2 + (e).w);                              \
        a0 = n0; a1 = n1; a2 = n2; a3 = n3;                                   \
        if ((dcur) == target && cap)                                          \
            saved = (ci == 0) ? n0 : (ci == 1) ? n1 : (ci == 2) ? n2 : n3;    \
    }

#define GROUP_SLOT(K)                                                         \
    {                                                                         \
        float4 b = qb##K, e = qe##K;                                          \
        qb##K = bl4[(size_t)(d0 + 8 + K) * (U_ / 4) + tx];                    \
        qe##K = em4[(size_t)(d0 + 8 + K) * (U_ / 4) + tx];                    \
        DP_STEP(b, e, d0 + K);                                                \
    }

__global__ void __launch_bounds__(32) dp_kernel(const int* __restrict__ lengths,
                                                const int* __restrict__ label_lengths)
{
    const int n  = blockIdx.x;
    const int tx = threadIdx.x;          // owns u = 4*tx .. 4*tx+3

    const float4* __restrict__ bl4 = g_blank4 + (size_t)n * DD_PAD * (U_ / 4);
    const float4* __restrict__ em4 = g_emit4  + (size_t)n * DD_PAD * (U_ / 4);

    const int t_idx  = lengths[n] - 1;
    const int u_idx  = label_lengths[n];
    const int target = t_idx + u_idx;

    float a0 = (tx == 0) ? 0.0f : NEGF;
    float a1 = NEGF, a2 = NEGF, a3 = NEGF;

    float saved = 0.0f;
    const bool cap = (tx == (u_idx >> 2));
    const int  ci  = u_idx & 3;

    // Prefetch rows 1..8 into named slots (row d is consumed at diagonal d).
    float4 qb0 = bl4[(size_t)1 * (U_ / 4) + tx], qe0 = em4[(size_t)1 * (U_ / 4) + tx];
    float4 qb1 = bl4[(size_t)2 * (U_ / 4) + tx], qe1 = em4[(size_t)2 * (U_ / 4) + tx];
    float4 qb2 = bl4[(size_t)3 * (U_ / 4) + tx], qe2 = em4[(size_t)3 * (U_ / 4) + tx];
    float4 qb3 = bl4[(size_t)4 * (U_ / 4) + tx], qe3 = em4[(size_t)4 * (U_ / 4) + tx];
    float4 qb4 = bl4[(size_t)5 * (U_ / 4) + tx], qe4 = em4[(size_t)5 * (U_ / 4) + tx];
    float4 qb5 = bl4[(size_t)6 * (U_ / 4) + tx], qe5 = em4[(size_t)6 * (U_ / 4) + tx];
    float4 qb6 = bl4[(size_t)7 * (U_ / 4) + tx], qe6 = em4[(size_t)7 * (U_ / 4) + tx];
    float4 qb7 = bl4[(size_t)8 * (U_ / 4) + tx], qe7 = em4[(size_t)8 * (U_ / 4) + tx];

    // Diagonals d = 1 .. 376 in 47 groups of 8; prefetch max row 384 < DD_PAD.
    for (int g = 0; g < 47; ++g) {
        const int d0 = 8 * g + 1;
        GROUP_SLOT(0) GROUP_SLOT(1) GROUP_SLOT(2) GROUP_SLOT(3)
        GROUP_SLOT(4) GROUP_SLOT(5) GROUP_SLOT(6) GROUP_SLOT(7)
    }

    // Remainder d = 377..382 (slots 0..5 hold rows 377..382).
    DP_STEP(qb0, qe0, 377); DP_STEP(qb1, qe1, 378); DP_STEP(qb2, qe2, 379);
    DP_STEP(qb3, qe3, 380); DP_STEP(qb4, qe4, 381); DP_STEP(qb5, qe5, 382);

    if (cap) {
        const float* blf = (const float*)g_blank4 + (size_t)n * DD_PAD * U_;
        float bfin = blf[(size_t)(target + 1) * U_ + u_idx];  // blank(t_idx,u_idx)
        g_cost[n] = -(saved + bfin);
    }
}

// ---------------------------------------------------------------------------
// Kernel 3: deterministic serial mean of the 16 per-example costs.
// ---------------------------------------------------------------------------
__global__ void finalize_kernel(float* __restrict__ out)
{
    float s = 0.0f;
#pragma unroll
    for (int i = 0; i < N_; ++i) s += g_cost[i];
    out[0] = s * (1.0f / N_);
}

// ---------------------------------------------------------------------------
extern "C" void kernel_launch(void* const* d_in, const int* in_sizes, int n_in,
                              void* d_out, int out_size)
{
    const float* log_probs     = (const float*)d_in[0];
    const int*   labels        = (const int*)  d_in[1];
    const int*   lengths       = (const int*)  d_in[2];
    const int*   label_lengths = (const int*)  d_in[3];
    float*       out           = (float*)d_out;

    gather_kernel  <<<N_ * DD, U_>>>(log_probs, labels);
    dp_kernel      <<<N_, 32>>>(lengths, label_lengths);
    finalize_kernel<<<1, 1>>>(out);
}

// round 7
// speedup vs baseline: 2.4355x; 1.0585x over previous
#include <cuda_runtime.h>
#include <cstdint>
#include <math.h>

// Problem shape (fixed by the dataset): N=16, T=256, U=128, V=256, blank = V-1.
#define N_  16
#define T_  256
#define U_  128
#define V_  256
#define DD  (T_ + U_ - 1)   // 383 anti-diagonals (d = 0 .. 382)
#define DD_PAD 400          // padded rows (cp.async prologue clamps at 399)

#define NEGF (-1e30f)

// Scratch (allocation-free rule: __device__ globals, zero-initialized).
// SHIFTED diagonal-major layout so diagonal d consumes exactly row d:
//   blank(n,t,u) stored at [n][t+u+1][u]
//   emit (n,t,u) stored at [n][t+u+1][u+1]
// Unwritten slots stay 0.0f; they only combine with NEG alphas -> harmless.
__device__ float4 g_blank4[N_ * DD_PAD * (U_ / 4)];
__device__ float4 g_emit4 [N_ * DD_PAD * (U_ / 4)];
__device__ float  g_cost  [N_];

// ---------------------------------------------------------------------------
// Kernel 1: gather. Each block: one n, four consecutive diagonal rows.
// All 8 loads per thread are issued unconditionally (clamped addresses) and
// front-batched for MLP; stores are predicated. Writes fully coalesced.
// ---------------------------------------------------------------------------
__global__ void __launch_bounds__(U_) gather_kernel(const float* __restrict__ lp,
                                                    const int*   __restrict__ labels)
{
    const int n  = blockIdx.x / 96;
    const int r0 = (blockIdx.x % 96) * 4 + 1;   // rows r0..r0+3 (1..384; 384 is a no-op row)
    const int c  = threadIdx.x;                  // column 0..127

    const int lbl = (c >= 1) ? __ldg(&labels[n * (U_ - 1) + (c - 1)]) : 0;

    float vb[4], ve[4];
    bool  okb[4], oke[4];
#pragma unroll
    for (int k = 0; k < 4; ++k) {
        const int r  = r0 + k;
        const int tb = r - 1 - c;                // blank(t=tb, u=c)
        const int te = r - c;                    // emit (t=te, u=c-1)
        okb[k] = (tb >= 0 && tb < T_);
        oke[k] = (c >= 1 && te >= 0 && te < T_);
        const int tbc = tb < 0 ? 0 : (tb > T_ - 1 ? T_ - 1 : tb);
        const int tec = te < 0 ? 0 : (te > T_ - 1 ? T_ - 1 : te);
        vb[k] = __ldcs(lp + ((((size_t)n * T_ + tbc) * U_ + c) * V_) + (V_ - 1));
        ve[k] = __ldcs(lp + ((((size_t)n * T_ + tec) * U_ + (c - (c >= 1))) * V_) + lbl);
    }

    float* bl = (float*)g_blank4;
    float* em = (float*)g_emit4;
#pragma unroll
    for (int k = 0; k < 4; ++k) {
        const size_t rowbase = ((size_t)n * DD_PAD + (r0 + k)) * U_;
        if (okb[k]) bl[rowbase + c] = vb[k];
        if (oke[k]) em[rowbase + c] = ve[k];
    }
}

// ---------------------------------------------------------------------------
// Kernel 2: wavefront DP. ONE WARP per example, 4 u-columns per thread.
// Operand rows flow through a 16-slot shared-memory ring filled by cp.async
// (no destination registers -> ~14 rows in flight ~ 840cy of latency cover).
// Each thread cp.async-copies exactly the 16B it later reads -> no barriers.
// ---------------------------------------------------------------------------
__device__ __forceinline__ float lse2(float a, float b) {
    float mx = fmaxf(a, b);
    float mn = fminf(a, b);
    return mx + 0.6931471805599453f *
                __log2f(1.0f + exp2f((mn - mx) * 1.4426950408889634f));
}

#define DP_STEP(b, e, dcur)                                                   \
    {                                                                         \
        float la = __shfl_up_sync(0xffffffffu, a3, 1);                        \
        float l0 = (tx == 0) ? NEGF : la;                                     \
        float n0 = lse2(a0 + (b).x, l0 + (e).x);                              \
        float n1 = lse2(a1 + (b).y, a0 + (e).y);                              \
        float n2 = lse2(a2 + (b).z, a1 + (e).z);                              \
        float n3 = lse2(a3 + (b).w, a2 + (e).w);                              \
        a0 = n0; a1 = n1; a2 = n2; a3 = n3;                                   \
        if ((dcur) == target && cap)                                          \
            saved = (ci == 0) ? n0 : (ci == 1) ? n1 : (ci == 2) ? n2 : n3;    \
    }

__global__ void __launch_bounds__(32) dp_kernel(const int* __restrict__ lengths,
                                                const int* __restrict__ label_lengths)
{
    __shared__ __align__(16) float sb[16 * U_];   // blank ring, slot = row & 15
    __shared__ __align__(16) float se[16 * U_];   // emit  ring

    const int n  = blockIdx.x;
    const int tx = threadIdx.x;                   // owns u = 4*tx .. 4*tx+3

    const float* __restrict__ bl = (const float*)g_blank4 + (size_t)n * DD_PAD * U_;
    const float* __restrict__ em = (const float*)g_emit4  + (size_t)n * DD_PAD * U_;

    const int t_idx  = lengths[n] - 1;
    const int u_idx  = label_lengths[n];
    const int target = t_idx + u_idx;

    float a0 = (tx == 0) ? 0.0f : NEGF;
    float a1 = NEGF, a2 = NEGF, a3 = NEGF;

    float saved = 0.0f;
    const bool cap = (tx == (u_idx >> 2));
    const int  ci  = u_idx & 3;

    const unsigned int sb_base = (unsigned int)__cvta_generic_to_shared(sb);
    const unsigned int se_base = (unsigned int)__cvta_generic_to_shared(se);
    const unsigned int lane_off = 16u * (unsigned int)tx;

    // --- async-copy one diagonal row rr into its ring slot ---
#define ISSUE_ROW(rr)                                                         \
    {                                                                         \
        int _rrc = (rr) < (DD_PAD - 1) ? (rr) : (DD_PAD - 1);                 \
        unsigned int _slot = ((unsigned int)(rr) & 15u) * (U_ * 4u)           \
                             + lane_off;                                      \
        const float* _gb = bl + (size_t)_rrc * U_ + 4 * tx;                   \
        const float* _ge = em + (size_t)_rrc * U_ + 4 * tx;                   \
        asm volatile("cp.async.ca.shared.global [%0], [%1], 16;"              \
                     :: "r"(sb_base + _slot), "l"(_gb));                      \
        asm volatile("cp.async.ca.shared.global [%0], [%1], 16;"              \
                     :: "r"(se_base + _slot), "l"(_ge));                      \
    }

    // Prologue: pairs q = 0..6 -> rows 1..14, one commit group per pair.
#pragma unroll
    for (int q = 0; q < 7; ++q) {
        ISSUE_ROW(2 * q + 1);
        ISSUE_ROW(2 * q + 2);
        asm volatile("cp.async.commit_group;" ::: "memory");
    }

    // Main loop: pair p computes diagonals d = 2p+1, 2p+2  (p = 0..190).
    for (int p = 0; p < 191; ++p) {
        // Wait until pair p's rows have landed (<=6 newer groups pending).
        asm volatile("cp.async.wait_group 6;" ::: "memory");

        // Keep the pipe full: issue pair p+7 (rows 2p+15, 2p+16; clamped).
        ISSUE_ROW(2 * p + 15);
        ISSUE_ROW(2 * p + 16);
        asm volatile("cp.async.commit_group;" ::: "memory");

        const int d1 = 2 * p + 1;
        {
            const int s = d1 & 15;
            float4 b = *(const float4*)&sb[s * U_ + 4 * tx];
            float4 e = *(const float4*)&se[s * U_ + 4 * tx];
            DP_STEP(b, e, d1);
        }
        {
            const int d2 = d1 + 1;
            const int s = d2 & 15;
            float4 b = *(const float4*)&sb[s * U_ + 4 * tx];
            float4 e = *(const float4*)&se[s * U_ + 4 * tx];
            DP_STEP(b, e, d2);
        }
    }

    if (cap) {
        float bfin = bl[(size_t)(target + 1) * U_ + u_idx];  // blank(t_idx, u_idx)
        g_cost[n] = -(saved + bfin);
    }
#undef ISSUE_ROW
}

// ---------------------------------------------------------------------------
// Kernel 3: deterministic serial mean of the 16 per-example costs.
// ---------------------------------------------------------------------------
__global__ void finalize_kernel(float* __restrict__ out)
{
    float s = 0.0f;
#pragma unroll
    for (int i = 0; i < N_; ++i) s += g_cost[i];
    out[0] = s * (1.0f / N_);
}

// ---------------------------------------------------------------------------
extern "C" void kernel_launch(void* const* d_in, const int* in_sizes, int n_in,
                              void* d_out, int out_size)
{
    const float* log_probs     = (const float*)d_in[0];
    const int*   labels        = (const int*)  d_in[1];
    const int*   lengths       = (const int*)  d_in[2];
    const int*   label_lengths = (const int*)  d_in[3];
    float*       out           = (float*)d_out;

    gather_kernel  <<<N_ * 96, U_>>>(log_probs, labels);
    dp_kernel      <<<N_, 32>>>(lengths, label_lengths);
    finalize_kernel<<<1, 1>>>(out);
}